// round 5
// baseline (speedup 1.0000x reference)
#include <cuda_runtime.h>
#include <cuda_bf16.h>
#include <cstdint>

#define MAXN 32768
#define MAXE 32768
#define MEM  150
#define JPAD 512

// ---------------- static device scratch (no allocations allowed) ------------
__device__ float g_state[MAXN * MEM];            // merged K/H per node
__device__ float g_stat [MAXN * JPAD];           // per-node static: Ww@w + Wt@tag + bias
__device__ float g_rel  [MAXN * JPAD];           // per-node: Wrel@rel
__device__ float g_leafpre[MAXN * JPAD];         // leaf GRU pre-activations
__device__ float g_WcombT[320 * JPAD];           // [w|tag] static weights, i-major
__device__ float g_leafWT [320 * JPAD];          // leaf_W transposed, i-major
__device__ float g_WrelT  [20  * JPAD];
__device__ float4 g_dyn4[76 * JPAD];             // interleaved dyn weights: vi 0..151=U, 152..303=Wk
__device__ float g_bias[JPAD];
__device__ float g_c0[JPAD];                     // leaf: leaf_U@leaf_h + leaf_b
__device__ int   g_edge_done[MAXE];
__device__ int   g_child_ready[MAXN];

// ---------------- sync helpers ----------------
__device__ __forceinline__ int ld_acq(const int* p) {
    int v;
    asm volatile("ld.acquire.gpu.global.b32 %0, [%1];" : "=r"(v) : "l"(p) : "memory");
    return v;
}
__device__ __forceinline__ void st_rel(int* p, int v) {
    asm volatile("st.release.gpu.global.b32 [%0], %1;" :: "l"(p), "r"(v) : "memory");
}
__device__ __forceinline__ float sigf(float x) { return 1.f / (1.f + expf(-x)); }

// ---------------- init ----------------
__global__ void k_init(int N, int E) {
    int stride = gridDim.x * blockDim.x;
    int t0 = blockIdx.x * blockDim.x + threadIdx.x;
    for (int i = t0; i < N * MEM; i += stride) g_state[i] = 0.f;
    for (int i = t0; i < E; i += stride) g_edge_done[i] = 0;
    for (int i = t0; i < N; i += stride) g_child_ready[i] = 0;
}

// ---------------- weight reshuffles ----------------
// node_W: (450,490) rows j, x layout: [word 0..299 | K 300..449 | rel 450..469 | tag 470..489]
// at_Wb:  (20,490) same x layout. Output column j: 0..449 GRU rows, 450..469 attention rows.
__global__ void k_build_big(const float* __restrict__ node_W, const float* __restrict__ node_U,
                            const float* __restrict__ at_Wb,  const float* __restrict__ leaf_W) {
    int idx = blockIdx.x * blockDim.x + threadIdx.x;
    if (idx >= 320 * JPAD) return;
    int i = idx / JPAD, j = idx % JPAD;
    // static [w(300)|tag(20)] combined weights, i-major
    float v = 0.f;
    if (j < 450)      v = (i < 300) ? node_W[j * 490 + i] : node_W[j * 490 + 470 + (i - 300)];
    else if (j < 470) v = (i < 300) ? at_Wb[(j - 450) * 490 + i]
                                    : at_Wb[(j - 450) * 490 + 470 + (i - 300)];
    g_WcombT[idx] = v;
    // leaf weights transposed: leaf_W (450,320)
    g_leafWT[idx] = (j < 450) ? leaf_W[j * 320 + i] : 0.f;
    // dynamic matrix, virtual index vi = i: 0..149 U rows, 152..301 Wk rows, pads 0
    if (i < 304) {
        float mv = 0.f;
        if (i < 150) {
            if (j < 450) mv = node_U[j * 150 + i];
        } else if (i >= 152) {
            int kk = i - 152;
            if (kk < 150) {
                if (j < 450)      mv = node_W[j * 490 + 300 + kk];
                else if (j < 470) mv = at_Wb[(j - 450) * 490 + 300 + kk];
            }
        }
        reinterpret_cast<float*>(g_dyn4)[((i >> 2) * JPAD + j) * 4 + (i & 3)] = mv;
    }
}

__global__ void k_build_small(const float* __restrict__ node_W, const float* __restrict__ at_Wb,
                              const float* __restrict__ node_b, const float* __restrict__ at_bb) {
    int idx = blockIdx.x * blockDim.x + threadIdx.x;
    if (idx < 20 * JPAD) {
        int i = idx / JPAD, j = idx % JPAD;
        float v = 0.f;
        if (j < 450)      v = node_W[j * 490 + 450 + i];
        else if (j < 470) v = at_Wb[(j - 450) * 490 + 450 + i];
        g_WrelT[idx] = v;
    } else if (idx < 21 * JPAD) {
        int j = idx - 20 * JPAD;
        g_bias[j] = (j < 450) ? node_b[j] : ((j < 470) ? at_bb[j - 450] : 0.f);
    }
}

__global__ void k_c0(const float* __restrict__ leaf_U, const float* __restrict__ leaf_h,
                     const float* __restrict__ leaf_b) {
    int j = threadIdx.x;
    if (j >= JPAD) return;
    float v = 0.f;
    if (j < 450) {
        v = leaf_b[j];
        for (int n = 0; n < MEM; n++) v += leaf_U[j * 150 + n] * leaf_h[n];
    }
    g_c0[j] = v;
}

// ---------------- tiled GEMM over [w|tag] (K=320) ----------------
// mode 0: g_stat[n][j]    = A[n] @ WcombT + bias   (M = N)
// mode 1: g_leafpre[l][j] = A[leaf_ids[l]] @ leafWT + c0   (M = L)
#define BM 64
#define BN 64
#define BK 16
__global__ void __launch_bounds__(256) k_gemm(int mode, int M,
                                              const float* __restrict__ w_emb,
                                              const float* __restrict__ tag_emb,
                                              const int* __restrict__ lids) {
    __shared__ float As[BK][BM + 4];
    __shared__ float Bs[BK][BN];
    const float* B = (mode == 0) ? g_WcombT : g_leafWT;
    int tid = threadIdx.x;
    int tx = tid & 15, ty = tid >> 4;
    int m0 = blockIdx.x * BM, j0 = blockIdx.y * BN;
    int ka = tid & 15, ma = tid >> 4;
    int jb = tid & 63, kb = tid >> 6;
    float acc[4][4] = {};
    for (int k0 = 0; k0 < 320; k0 += BK) {
        #pragma unroll
        for (int it = 0; it < 4; it++) {
            int r = m0 + ma + 16 * it;
            if (r >= M) r = M - 1;
            int row = (mode == 1) ? lids[r] : r;
            int i = k0 + ka;
            As[ka][ma + 16 * it] = (i < 300) ? w_emb[row * 300 + i]
                                             : tag_emb[row * 20 + (i - 300)];
        }
        #pragma unroll
        for (int it = 0; it < 4; it++)
            Bs[kb + 4 * it][jb] = B[(k0 + kb + 4 * it) * JPAD + (j0 + jb)];
        __syncthreads();
        #pragma unroll
        for (int k = 0; k < BK; k++) {
            float4 a4 = *(const float4*)&As[k][ty * 4];
            float4 b4 = *(const float4*)&Bs[k][tx * 4];
            float av[4] = {a4.x, a4.y, a4.z, a4.w};
            float bv[4] = {b4.x, b4.y, b4.z, b4.w};
            #pragma unroll
            for (int mm = 0; mm < 4; mm++)
                #pragma unroll
                for (int jj = 0; jj < 4; jj++)
                    acc[mm][jj] = fmaf(av[mm], bv[jj], acc[mm][jj]);
        }
        __syncthreads();
    }
    #pragma unroll
    for (int mm = 0; mm < 4; mm++) {
        int r = m0 + ty * 4 + mm;
        if (r >= M) continue;
        #pragma unroll
        for (int jj = 0; jj < 4; jj++) {
            int j = j0 + tx * 4 + jj;
            if (mode == 0) g_stat[r * JPAD + j]    = acc[mm][jj] + g_bias[j];
            else           g_leafpre[r * JPAD + j] = acc[mm][jj] + g_c0[j];
        }
    }
}

// ---------------- rel projection (K=20) ----------------
__global__ void __launch_bounds__(512) k_relpart(const float* __restrict__ rel_emb) {
    int n = blockIdx.x, j = threadIdx.x;
    float acc = 0.f;
    #pragma unroll
    for (int q = 0; q < 20; q++)
        acc = fmaf(g_WrelT[q * JPAD + j], __ldg(&rel_emb[n * 20 + q]), acc);
    g_rel[n * JPAD + j] = acc;
}

// ---------------- leaf epilogue ----------------
__global__ void k_leafcomb(const int* __restrict__ lids, const float* __restrict__ leaf_h, int L) {
    int idx = blockIdx.x * blockDim.x + threadIdx.x;
    if (idx >= L * MEM) return;
    int l = idx / MEM, m = idx % MEM;
    float z  = sigf (g_leafpre[l * JPAD + m]);
    float r  = sigf (g_leafpre[l * JPAD + 150 + m]);
    float ht = tanhf(g_leafpre[l * JPAD + 300 + m]);
    g_state[lids[l] * MEM + m] = r * leaf_h[m] + (1.f - z) * ht;
}

__global__ void k_leafready(const int* __restrict__ lids, int L) {
    int l = blockIdx.x * blockDim.x + threadIdx.x;
    if (l < L) g_child_ready[lids[l]] = 1;
}

// ---------------- persistent dependency-driven edge kernel ----------------
__global__ void __launch_bounds__(512, 1) k_edges(const int* __restrict__ ed, int E,
                                                  const float* __restrict__ at_Wa,
                                                  const float* __restrict__ at_ba) {
    __shared__ __align__(16) float vsm[304];   // [h(150),0,0, k(150),0,0]
    __shared__ float spre[JPAD];
    __shared__ float s_a;
    int tid = threadIdx.x;
    float ba = *at_ba;

    for (int e = blockIdx.x; e < E; e += gridDim.x) {
        int p = ed[2 * e], c = ed[2 * e + 1];
        if (tid == 0) {
            if (e > 0 && ed[2 * (e - 1)] == p) {
                while (ld_acq(&g_edge_done[e - 1]) == 0) __nanosleep(40);
            }
            while (ld_acq(&g_child_ready[c]) == 0) __nanosleep(40);
        }
        __syncthreads();
        // load h = state[p], k = state[c] (L2-coherent loads)
        if (tid < 152)       vsm[tid] = (tid < 150) ? __ldcg(&g_state[p * MEM + tid]) : 0.f;
        else if (tid < 304) { int i = tid - 152;
                              vsm[tid] = (i < 150) ? __ldcg(&g_state[c * MEM + i]) : 0.f; }
        __syncthreads();

        int j = tid;
        float acc = __ldcg(&g_stat[p * JPAD + j]) + __ldcg(&g_rel[c * JPAD + j]);
        #pragma unroll 4
        for (int r = 0; r < 76; r++) {
            float4 d = g_dyn4[r * JPAD + j];
            float4 v = reinterpret_cast<const float4*>(vsm)[r];
            acc += d.x * v.x + d.y * v.y + d.z * v.z + d.w * v.w;
        }
        spre[j] = acc;
        __syncthreads();

        if (tid == 0) {
            float s = 0.f;
            #pragma unroll
            for (int q = 0; q < 20; q++) s += at_Wa[q] * tanhf(spre[450 + q]);
            s_a = sigf(s + ba);
        }
        __syncthreads();

        if (tid < 150) {
            float h  = vsm[tid];
            float z  = sigf(spre[tid]);
            float r_ = sigf(spre[150 + tid]);
            float ht = tanhf(spre[300 + tid]);
            float m  = r_ * h + (1.f - z) * ht;
            float a  = s_a;
            g_state[p * MEM + tid] = a * m + (1.f - a) * h;
        }
        __syncthreads();
        if (tid == 0) {
            __threadfence();
            st_rel(&g_edge_done[e], 1);
            bool last = (e == E - 1) || (ed[2 * (e + 1)] != p);
            if (last) st_rel(&g_child_ready[p], 1);
        }
    }
}

__global__ void k_out(float* __restrict__ out) {
    int m = threadIdx.x;
    if (m < MEM) out[m] = g_state[m];
}

// ---------------- launch ----------------
extern "C" void kernel_launch(void* const* d_in, const int* in_sizes, int n_in,
                              void* d_out, int out_size) {
    const float* w_emb   = (const float*)d_in[0];
    const float* tag_emb = (const float*)d_in[1];
    const float* rel_emb = (const float*)d_in[2];
    const float* leaf_h  = (const float*)d_in[3];
    const float* leaf_W  = (const float*)d_in[4];
    const float* leaf_U  = (const float*)d_in[5];
    const float* leaf_b  = (const float*)d_in[6];
    const float* node_W  = (const float*)d_in[7];
    const float* node_U  = (const float*)d_in[8];
    const float* node_b  = (const float*)d_in[9];
    const float* at_Wb   = (const float*)d_in[10];
    const float* at_bb   = (const float*)d_in[11];
    const float* at_Wa   = (const float*)d_in[12];
    const float* at_ba   = (const float*)d_in[13];
    const int*   edges   = (const int*)d_in[14];
    const int*   lids    = (const int*)d_in[15];

    int N = in_sizes[0] / 300;
    int E = in_sizes[14] / 2;
    int L = in_sizes[15];

    k_init<<<256, 256>>>(N, E);
    k_build_big<<<(320 * JPAD + 255) / 256, 256>>>(node_W, node_U, at_Wb, leaf_W);
    k_build_small<<<(21 * JPAD + 255) / 256, 256>>>(node_W, at_Wb, node_b, at_bb);
    k_c0<<<1, 512>>>(leaf_U, leaf_h, leaf_b);
    k_gemm<<<dim3((N + BM - 1) / BM, JPAD / BN), 256>>>(0, N, w_emb, tag_emb, lids);
    k_gemm<<<dim3((L + BM - 1) / BM, JPAD / BN), 256>>>(1, L, w_emb, tag_emb, lids);
    k_relpart<<<N, 512>>>(rel_emb);
    k_leafcomb<<<(L * MEM + 255) / 256, 256>>>(lids, leaf_h, L);
    k_leafready<<<(L + 255) / 256, 256>>>(lids, L);
    k_edges<<<128, 512>>>(edges, E, at_Wa, at_ba);
    k_out<<<1, 256>>>((float*)d_out);
}